// round 1
// baseline (speedup 1.0000x reference)
#include <cuda_runtime.h>
#include <math.h>

#define Bc 128
#define Nc 2048
#define Mc 128
#define NBLK 32            // n-blocks per batch
#define ROWS_PER_BLK 64    // 8 warps * 8 rows
#define OUT_STRIDE (Mc + 2*Nc)   // 4224

// scratch (static device globals — no allocation allowed)
__device__ float g_dot[Bc * Nc];            // dot/nm per (b,n)
__device__ float g_part[Bc * NBLK * Mc];    // per-block column partial sums

// ---------------------------------------------------------------------------
// Pass 1: single sweep over memory [B,N,M].
// Per row n: dot((mem+eps),(k+eps)) and ||mem+eps|| -> g_dot = dot/nm.
// Per block: partial column sums of raw memory -> g_part.
// ---------------------------------------------------------------------------
__global__ void __launch_bounds__(256) ntm_pass1(
    const float* __restrict__ mem, const float* __restrict__ k)
{
    const int b    = blockIdx.y;
    const int blk  = blockIdx.x;
    const int warp = threadIdx.x >> 5;
    const int lane = threadIdx.x & 31;

    // k row (with offset), 4 elements per lane
    float4 kv = ((const float4*)(k + b * Mc))[lane];
    kv.x += 1e-6f; kv.y += 1e-6f; kv.z += 1e-6f; kv.w += 1e-6f;

    const int n0 = blk * ROWS_PER_BLK + warp * 8;
    const float4* mp = (const float4*)(mem + ((size_t)b * Nc + n0) * Mc);

    // front-batch 8 row loads (MLP=8)
    float4 v[8];
#pragma unroll
    for (int i = 0; i < 8; i++) v[i] = mp[i * 32 + lane];

    float cs0 = 0.f, cs1 = 0.f, cs2 = 0.f, cs3 = 0.f;

#pragma unroll
    for (int i = 0; i < 8; i++) {
        float4 t = v[i];
        cs0 += t.x; cs1 += t.y; cs2 += t.z; cs3 += t.w;   // raw memory colsum
        float ax = t.x + 1e-6f, ay = t.y + 1e-6f;
        float az = t.z + 1e-6f, aw = t.w + 1e-6f;
        float dot = ax * kv.x + ay * kv.y + az * kv.z + aw * kv.w;
        float sq  = ax * ax + ay * ay + az * az + aw * aw;
#pragma unroll
        for (int off = 16; off; off >>= 1) {
            dot += __shfl_xor_sync(0xFFFFFFFFu, dot, off);
            sq  += __shfl_xor_sync(0xFFFFFFFFu, sq,  off);
        }
        if (lane == 0) {
            float nm = fmaxf(sqrtf(sq), 1e-8f);
            g_dot[b * Nc + n0 + i] = dot / nm;
        }
    }

    // cross-warp colsum reduce, then one partial row per block
    __shared__ float s_cs[8][Mc];
    int m = lane * 4;
    s_cs[warp][m + 0] = cs0;
    s_cs[warp][m + 1] = cs1;
    s_cs[warp][m + 2] = cs2;
    s_cs[warp][m + 3] = cs3;
    __syncthreads();
    if (threadIdx.x < Mc) {
        float s = 0.f;
#pragma unroll
        for (int w = 0; w < 8; w++) s += s_cs[w][threadIdx.x];
        g_part[((size_t)b * NBLK + blk) * Mc + threadIdx.x] = s;
    }
}

// ---------------------------------------------------------------------------
// Pass 2: one block per batch. nk, softmax(beta*K), w_g, s_b scalar, r_t.
// ---------------------------------------------------------------------------
__global__ void __launch_bounds__(256) ntm_pass2(
    const float* __restrict__ k,     const float* __restrict__ beta,
    const float* __restrict__ gt,    const float* __restrict__ wprev,
    const float* __restrict__ gamma, const float* __restrict__ e,
    const float* __restrict__ a,     float* __restrict__ out)
{
    const int b   = blockIdx.x;
    const int tid = threadIdx.x;

    __shared__ float s_val[Nc];   // logits, then exp values
    __shared__ float red[256];
    __shared__ float s_scalar[3]; // nk, max, sums

    // ---- nk = max(||k+eps||, 1e-8) ----
    float kk = 0.f;
    if (tid < Mc) { float t = k[b * Mc + tid] + 1e-6f; kk = t * t; }
    red[tid] = kk; __syncthreads();
#pragma unroll
    for (int s = 128; s > 0; s >>= 1) {
        if (tid < s) red[tid] += red[tid + s];
        __syncthreads();
    }
    if (tid == 0) s_scalar[0] = fmaxf(sqrtf(red[0]), 1e-8f);
    __syncthreads();
    const float scale = beta[b] / s_scalar[0];

    // ---- logits + max ----
    float lmax = -1e30f;
#pragma unroll
    for (int i = 0; i < Nc / 256; i++) {
        int n = tid + i * 256;
        float lg = g_dot[b * Nc + n] * scale;
        s_val[n] = lg;
        lmax = fmaxf(lmax, lg);
    }
    red[tid] = lmax; __syncthreads();
#pragma unroll
    for (int s = 128; s > 0; s >>= 1) {
        if (tid < s) red[tid] = fmaxf(red[tid], red[tid + s]);
        __syncthreads();
    }
    if (tid == 0) s_scalar[1] = red[0];
    __syncthreads();
    const float maxv = s_scalar[1];

    // ---- sum(exp) and sum(wprev^gamma) ----
    const float gam = gamma[b];
    float sume = 0.f, sump = 0.f;
#pragma unroll
    for (int i = 0; i < Nc / 256; i++) {
        int n = tid + i * 256;
        float ex = __expf(s_val[n] - maxv);
        s_val[n] = ex;
        sume += ex;
        sump += powf(wprev[b * Nc + n], gam);
    }
    red[tid] = sume; __syncthreads();
#pragma unroll
    for (int s = 128; s > 0; s >>= 1) {
        if (tid < s) red[tid] += red[tid + s];
        __syncthreads();
    }
    if (tid == 0) s_scalar[1] = red[0];
    __syncthreads();
    red[tid] = sump; __syncthreads();
#pragma unroll
    for (int s = 128; s > 0; s >>= 1) {
        if (tid < s) red[tid] += red[tid + s];
        __syncthreads();
    }
    if (tid == 0) s_scalar[2] = red[0] + 1e-6f;
    __syncthreads();

    const float inv_sum = 1.f / s_scalar[1];
    const float sB      = s_scalar[2];          // the broadcast w_t scalar
    const float gv      = gt[b];
    float* ob = out + (size_t)b * OUT_STRIDE;

    // ---- w_t (broadcast scalar) and w_g outputs ----
#pragma unroll
    for (int i = 0; i < Nc / 256; i++) {
        int n = tid + i * 256;
        float wc = s_val[n] * inv_sum;
        ob[Mc + n]      = sB;
        ob[Mc + Nc + n] = gv * wc + (1.f - gv) * wprev[b * Nc + n];
    }

    // ---- r_t = sB * ((1 - sB*e) * colsum + N * sB * a) ----
    if (tid < Mc) {
        float Sm = 0.f;
#pragma unroll
        for (int j = 0; j < NBLK; j++)
            Sm += g_part[((size_t)b * NBLK + j) * Mc + tid];
        float ev = e[b * Mc + tid];
        float av = a[b * Mc + tid];
        ob[tid] = sB * ((1.f - sB * ev) * Sm + (float)Nc * sB * av);
    }
}

extern "C" void kernel_launch(void* const* d_in, const int* in_sizes, int n_in,
                              void* d_out, int out_size)
{
    const float* mem   = (const float*)d_in[0];
    const float* k     = (const float*)d_in[1];
    const float* beta  = (const float*)d_in[2];
    const float* gt    = (const float*)d_in[3];
    const float* wprev = (const float*)d_in[4];
    // d_in[5] = s_t (unused by the reference's live outputs)
    const float* gamma = (const float*)d_in[6];
    const float* e     = (const float*)d_in[7];
    const float* a     = (const float*)d_in[8];
    float* out = (float*)d_out;

    ntm_pass1<<<dim3(NBLK, Bc), 256>>>(mem, k);
    ntm_pass2<<<Bc, 256>>>(k, beta, gt, wprev, gamma, e, a, out);
}

// round 2
// speedup vs baseline: 1.2625x; 1.2625x over previous
#include <cuda_runtime.h>
#include <math.h>

#define Bc 128
#define Nc 2048
#define Mc 128
#define NBLK 32            // n-blocks per batch
#define ROWS_PER_BLK 64    // 8 warps * 8 rows
#define OUT_STRIDE (Mc + 2*Nc)   // 4224

// scratch (static device globals — no allocation allowed)
__device__ float g_dot[Bc * Nc];            // dot/nm per (b,n)
__device__ float g_part[Bc * NBLK * Mc];    // per-block column partial sums

// ---------------------------------------------------------------------------
// Pass 1: single sweep over memory [B,N,M].
// Per row n: dot((mem+eps),(k+eps)) and ||mem+eps|| -> g_dot = dot/nm.
// Per block: partial column sums of raw memory -> g_part.
// ---------------------------------------------------------------------------
__global__ void __launch_bounds__(256) ntm_pass1(
    const float* __restrict__ mem, const float* __restrict__ k)
{
    const int b    = blockIdx.y;
    const int blk  = blockIdx.x;
    const int warp = threadIdx.x >> 5;
    const int lane = threadIdx.x & 31;

    // k row (with offset), 4 elements per lane
    float4 kv = ((const float4*)(k + b * Mc))[lane];
    kv.x += 1e-6f; kv.y += 1e-6f; kv.z += 1e-6f; kv.w += 1e-6f;

    const int n0 = blk * ROWS_PER_BLK + warp * 8;
    const float4* mp = (const float4*)(mem + ((size_t)b * Nc + n0) * Mc);

    // front-batch 8 row loads (MLP=8)
    float4 v[8];
#pragma unroll
    for (int i = 0; i < 8; i++) v[i] = mp[i * 32 + lane];

    float cs0 = 0.f, cs1 = 0.f, cs2 = 0.f, cs3 = 0.f;

#pragma unroll
    for (int i = 0; i < 8; i++) {
        float4 t = v[i];
        cs0 += t.x; cs1 += t.y; cs2 += t.z; cs3 += t.w;   // raw memory colsum
        float ax = t.x + 1e-6f, ay = t.y + 1e-6f;
        float az = t.z + 1e-6f, aw = t.w + 1e-6f;
        float dot = ax * kv.x + ay * kv.y + az * kv.z + aw * kv.w;
        float sq  = ax * ax + ay * ay + az * az + aw * aw;
#pragma unroll
        for (int off = 16; off; off >>= 1) {
            dot += __shfl_xor_sync(0xFFFFFFFFu, dot, off);
            sq  += __shfl_xor_sync(0xFFFFFFFFu, sq,  off);
        }
        if (lane == 0) {
            // nm is ~sqrt(M) >> 1e-8, clamp via tiny floor inside rsqrt
            g_dot[b * Nc + n0 + i] = dot * rsqrtf(fmaxf(sq, 1e-16f));
        }
    }

    // cross-warp colsum reduce, then one partial row per block
    __shared__ float s_cs[8][Mc];
    int m = lane * 4;
    s_cs[warp][m + 0] = cs0;
    s_cs[warp][m + 1] = cs1;
    s_cs[warp][m + 2] = cs2;
    s_cs[warp][m + 3] = cs3;
    __syncthreads();
    if (threadIdx.x < Mc) {
        float s = 0.f;
#pragma unroll
        for (int w = 0; w < 8; w++) s += s_cs[w][threadIdx.x];
        g_part[((size_t)b * NBLK + blk) * Mc + threadIdx.x] = s;
    }
}

// ---------------------------------------------------------------------------
// Pass 2: one block (512 thr) per batch. 2 block reductions total.
// ---------------------------------------------------------------------------
__global__ void __launch_bounds__(512) ntm_pass2(
    const float* __restrict__ k,     const float* __restrict__ beta,
    const float* __restrict__ gt,    const float* __restrict__ wprev,
    const float* __restrict__ gamma, const float* __restrict__ e,
    const float* __restrict__ a,     float* __restrict__ out)
{
    const int b    = blockIdx.x;
    const int tid  = threadIdx.x;
    const int warp = tid >> 5;
    const int lane = tid & 31;

    __shared__ float smax[16];
    __shared__ float sadd[16];
    __shared__ float s_nk, s_max, s_sum, s_pow;

    // ---- per-thread data: one float4 of g_dot and wprev each ----
    const float4 gd = ((const float4*)(g_dot + b * Nc))[tid];
    const float4 wp = ((const float4*)(wprev + b * Nc))[tid];
    const float  gam = gamma[b];

    // ---- warp 0 computes nk = max(||k+eps||, 1e-8) (no barrier needed) ----
    if (warp == 0) {
        float4 kv = ((const float4*)(k + b * Mc))[lane];
        float ax = kv.x + 1e-6f, ay = kv.y + 1e-6f;
        float az = kv.z + 1e-6f, aw = kv.w + 1e-6f;
        float kk = ax*ax + ay*ay + az*az + aw*aw;
#pragma unroll
        for (int off = 16; off; off >>= 1)
            kk += __shfl_xor_sync(0xFFFFFFFFu, kk, off);
        if (lane == 0) s_nk = fmaxf(sqrtf(kk), 1e-8f);
    }

    // ---- combined block reduce: (max of g_dot, sum of wprev^gamma) ----
    float vmax = fmaxf(fmaxf(gd.x, gd.y), fmaxf(gd.z, gd.w));
    float vadd = __powf(wp.x, gam) + __powf(wp.y, gam)
               + __powf(wp.z, gam) + __powf(wp.w, gam);
#pragma unroll
    for (int off = 16; off; off >>= 1) {
        vmax = fmaxf(vmax, __shfl_xor_sync(0xFFFFFFFFu, vmax, off));
        vadd += __shfl_xor_sync(0xFFFFFFFFu, vadd, off);
    }
    if (lane == 0) { smax[warp] = vmax; sadd[warp] = vadd; }
    __syncthreads();
    if (warp == 0) {
        float m = (lane < 16) ? smax[lane] : -1e30f;
        float s = (lane < 16) ? sadd[lane] : 0.f;
#pragma unroll
        for (int off = 8; off; off >>= 1) {
            m = fmaxf(m, __shfl_xor_sync(0xFFFFFFFFu, m, off));
            s += __shfl_xor_sync(0xFFFFFFFFu, s, off);
        }
        if (lane == 0) { s_max = m; s_pow = s + 1e-6f; }
    }
    __syncthreads();

    // scale >= 0  =>  max(scale*K) = scale*max(K)
    const float scale = beta[b] / s_nk;
    const float maxl  = scale * s_max;

    // ---- exp + sum reduce ----
    float4 ex;
    ex.x = __expf(scale * gd.x - maxl);
    ex.y = __expf(scale * gd.y - maxl);
    ex.z = __expf(scale * gd.z - maxl);
    ex.w = __expf(scale * gd.w - maxl);
    float se = ex.x + ex.y + ex.z + ex.w;
#pragma unroll
    for (int off = 16; off; off >>= 1)
        se += __shfl_xor_sync(0xFFFFFFFFu, se, off);
    if (lane == 0) sadd[warp] = se;
    __syncthreads();
    if (warp == 0) {
        float s = (lane < 16) ? sadd[lane] : 0.f;
#pragma unroll
        for (int off = 8; off; off >>= 1)
            s += __shfl_xor_sync(0xFFFFFFFFu, s, off);
        if (lane == 0) s_sum = s;
    }
    __syncthreads();

    const float inv_sum = 1.f / s_sum;
    const float sB      = s_pow;        // broadcast w_t scalar
    const float gv      = gt[b];
    const float og      = 1.f - gv;
    float* ob = out + (size_t)b * OUT_STRIDE;

    // ---- w_t (broadcast scalar) and w_g outputs, float4 stores ----
    float4 wt4 = make_float4(sB, sB, sB, sB);
    ((float4*)(ob + Mc))[tid] = wt4;
    float4 wg;
    wg.x = gv * ex.x * inv_sum + og * wp.x;
    wg.y = gv * ex.y * inv_sum + og * wp.y;
    wg.z = gv * ex.z * inv_sum + og * wp.z;
    wg.w = gv * ex.w * inv_sum + og * wp.w;
    ((float4*)(ob + Mc + Nc))[tid] = wg;

    // ---- r_t = sB * ((1 - sB*e) * colsum + N * sB * a) ----
    if (tid < Mc) {
        float Sm = 0.f;
#pragma unroll
        for (int j = 0; j < NBLK; j++)
            Sm += g_part[((size_t)b * NBLK + j) * Mc + tid];
        float ev = e[b * Mc + tid];
        float av = a[b * Mc + tid];
        ob[tid] = sB * ((1.f - sB * ev) * Sm + (float)Nc * sB * av);
    }
}

extern "C" void kernel_launch(void* const* d_in, const int* in_sizes, int n_in,
                              void* d_out, int out_size)
{
    const float* mem   = (const float*)d_in[0];
    const float* k     = (const float*)d_in[1];
    const float* beta  = (const float*)d_in[2];
    const float* gt    = (const float*)d_in[3];
    const float* wprev = (const float*)d_in[4];
    // d_in[5] = s_t (unused by the reference's live outputs)
    const float* gamma = (const float*)d_in[6];
    const float* e     = (const float*)d_in[7];
    const float* a     = (const float*)d_in[8];
    float* out = (float*)d_out;

    ntm_pass1<<<dim3(NBLK, Bc), 256>>>(mem, k);
    ntm_pass2<<<Bc, 512>>>(k, beta, gt, wprev, gamma, e, a, out);
}

// round 3
// speedup vs baseline: 1.2686x; 1.0048x over previous
#include <cuda_runtime.h>
#include <math.h>

#define Bc 128
#define Nc 2048
#define Mc 128
#define NBLK 32            // n-blocks per batch (64 rows each)
#define OUT_STRIDE (Mc + 2*Nc)   // 4224

// scratch (static device globals — no allocation allowed)
__device__ float g_exp [Bc * Nc];           // exp(scale*cos) per (b,n)
__device__ float g_part[Bc * NBLK * Mc];    // per-block column partial sums
__device__ float g_bsum[Bc * NBLK];         // per-block partial sum of exp
__device__ float g_bpow[Bc * NBLK];         // per-block partial sum of wprev^gamma

// ---------------------------------------------------------------------------
// Pass 1: single sweep over memory [B,N,M].
//   per row n : exp( beta/nk * dot(mem,k+eps)/||mem|| )  -> g_exp
//   per block : column partial sums of memory           -> g_part
//               partial sum of exp                       -> g_bsum
//               partial sum of wprev^gamma               -> g_bpow
// ---------------------------------------------------------------------------
__global__ void __launch_bounds__(256) ntm_pass1(
    const float* __restrict__ mem,   const float* __restrict__ k,
    const float* __restrict__ beta,  const float* __restrict__ wprev,
    const float* __restrict__ gamma)
{
    const int b    = blockIdx.y;
    const int blk  = blockIdx.x;
    const int warp = threadIdx.x >> 5;
    const int lane = threadIdx.x & 31;

    // k row (with eps), 4 elements per lane
    float4 kv = ((const float4*)(k + b * Mc))[lane];
    kv.x += 1e-6f; kv.y += 1e-6f; kv.z += 1e-6f; kv.w += 1e-6f;

    // per-warp nk and scale (redundant across warps, no barrier)
    float kk = kv.x*kv.x + kv.y*kv.y + kv.z*kv.z + kv.w*kv.w;
#pragma unroll
    for (int off = 16; off; off >>= 1)
        kk += __shfl_xor_sync(0xFFFFFFFFu, kk, off);
    const float scale = beta[b] * rsqrtf(fmaxf(kk, 1e-16f));

    const int n0 = blk * 64 + warp * 8;
    const float4* mp = (const float4*)(mem + ((size_t)b * Nc + n0) * Mc);

    // front-batch 8 row loads (MLP=8)
    float4 v[8];
#pragma unroll
    for (int i = 0; i < 8; i++) v[i] = mp[i * 32 + lane];

    // raw column sums
    float cs0 = 0.f, cs1 = 0.f, cs2 = 0.f, cs3 = 0.f;
#pragma unroll
    for (int i = 0; i < 8; i++) {
        cs0 += v[i].x; cs1 += v[i].y; cs2 += v[i].z; cs3 += v[i].w;
    }

    // 16 per-lane partials: r[0..7]=dot_i, r[8..15]=sq_i  (eps on mem dropped)
    float r[16];
#pragma unroll
    for (int i = 0; i < 8; i++) {
        float4 t = v[i];
        r[i]     = t.x*kv.x + t.y*kv.y + t.z*kv.z + t.w*kv.w;
        r[i + 8] = t.x*t.x  + t.y*t.y  + t.z*t.z  + t.w*t.w;
    }

    // multi-value butterfly: 16 reductions over 32 lanes in 16 shuffles
#pragma unroll
    for (int o = 16, nv = 16; o >= 2; o >>= 1, nv >>= 1) {
        const int half = nv >> 1;
#pragma unroll
        for (int j = 0; j < half; j++) {
            float send = (lane & o) ? r[j] : r[j + half];
            float recv = __shfl_xor_sync(0xFFFFFFFFu, send, o);
            r[j] = ((lane & o) ? r[j + half] : r[j]) + recv;
        }
    }
    r[0] += __shfl_xor_sync(0xFFFFFFFFu, r[0], 1);
    // now: lanes 2i,2i+1 (i<8) hold dot_i ; lanes 16+2i hold sq_i
    float other = __shfl_xor_sync(0xFFFFFFFFu, r[0], 16);  // sq_i on low lanes

    float ex = 0.f;
    const bool writer = (lane < 16) && !(lane & 1);
    if (writer) {
        int i = lane >> 1;
        ex = __expf(scale * r[0] * rsqrtf(fmaxf(other, 1e-16f)));
        g_exp[b * Nc + n0 + i] = ex;
    }
    // warp-local exp sum over the 8 writer lanes (even lanes 0..14)
    ex += __shfl_xor_sync(0xFFFFFFFFu, ex, 2);
    ex += __shfl_xor_sync(0xFFFFFFFFu, ex, 4);
    ex += __shfl_xor_sync(0xFFFFFFFFu, ex, 8);

    // wprev^gamma partials: threads 0..63 (warps 0,1)
    float pw = 0.f;
    if (threadIdx.x < 64)
        pw = __powf(wprev[b * Nc + blk * 64 + threadIdx.x], gamma[b]);
#pragma unroll
    for (int off = 16; off; off >>= 1)
        pw += __shfl_xor_sync(0xFFFFFFFFu, pw, off);

    __shared__ float s_cs[8][Mc];
    __shared__ float s_exw[8];
    __shared__ float s_pww[2];
    {
        int m = lane * 4;
        s_cs[warp][m + 0] = cs0;
        s_cs[warp][m + 1] = cs1;
        s_cs[warp][m + 2] = cs2;
        s_cs[warp][m + 3] = cs3;
        if (lane == 0) {
            s_exw[warp] = ex;
            if (warp < 2) s_pww[warp] = pw;
        }
    }
    __syncthreads();

    if (threadIdx.x < Mc) {
        float s = 0.f;
#pragma unroll
        for (int w = 0; w < 8; w++) s += s_cs[w][threadIdx.x];
        g_part[((size_t)b * NBLK + blk) * Mc + threadIdx.x] = s;
    }
    if (threadIdx.x == 0) {
        float s = 0.f;
#pragma unroll
        for (int w = 0; w < 8; w++) s += s_exw[w];
        g_bsum[b * NBLK + blk] = s;
        g_bpow[b * NBLK + blk] = s_pww[0] + s_pww[1];
    }
}

// ---------------------------------------------------------------------------
// Pass 2: grid (4 splits, B), 128 threads. Tiny 32-element reduce + elementwise.
// ---------------------------------------------------------------------------
__global__ void __launch_bounds__(128) ntm_pass2(
    const float* __restrict__ gt,   const float* __restrict__ wprev,
    const float* __restrict__ e,    const float* __restrict__ a,
    float* __restrict__ out)
{
    const int b     = blockIdx.y;
    const int split = blockIdx.x;
    const int tid   = threadIdx.x;

    __shared__ float s_inv, s_sB;
    if (tid < 32) {
        float es = g_bsum[b * NBLK + tid];
        float pw = g_bpow[b * NBLK + tid];
#pragma unroll
        for (int off = 16; off; off >>= 1) {
            es += __shfl_xor_sync(0xFFFFFFFFu, es, off);
            pw += __shfl_xor_sync(0xFFFFFFFFu, pw, off);
        }
        if (tid == 0) { s_inv = 1.f / es; s_sB = pw + 1e-6f; }
    }
    __syncthreads();

    const float inv = s_inv;
    const float sB  = s_sB;
    const float gv  = gt[b];
    const float og  = 1.f - gv;
    float* ob = out + (size_t)b * OUT_STRIDE;

    const int n4 = split * 128 + tid;   // float4 index into [Nc]
    const float4 ex = ((const float4*)(g_exp  + b * Nc))[n4];
    const float4 wp = ((const float4*)(wprev + b * Nc))[n4];

    ((float4*)(ob + Mc))[n4] = make_float4(sB, sB, sB, sB);
    float4 wg;
    wg.x = gv * ex.x * inv + og * wp.x;
    wg.y = gv * ex.y * inv + og * wp.y;
    wg.z = gv * ex.z * inv + og * wp.z;
    wg.w = gv * ex.w * inv + og * wp.w;
    ((float4*)(ob + Mc + Nc))[n4] = wg;

    if (split == 0) {
        // r_t = sB * ((1 - sB*e) * colsum + N * sB * a)
        float Sm = 0.f;
#pragma unroll
        for (int j = 0; j < NBLK; j++)
            Sm += g_part[((size_t)b * NBLK + j) * Mc + tid];
        float ev = e[b * Mc + tid];
        float av = a[b * Mc + tid];
        ob[tid] = sB * ((1.f - sB * ev) * Sm + (float)Nc * sB * av);
    }
}

extern "C" void kernel_launch(void* const* d_in, const int* in_sizes, int n_in,
                              void* d_out, int out_size)
{
    const float* mem   = (const float*)d_in[0];
    const float* k     = (const float*)d_in[1];
    const float* beta  = (const float*)d_in[2];
    const float* gt    = (const float*)d_in[3];
    const float* wprev = (const float*)d_in[4];
    // d_in[5] = s_t (unused by the reference's live outputs)
    const float* gamma = (const float*)d_in[6];
    const float* e     = (const float*)d_in[7];
    const float* a     = (const float*)d_in[8];
    float* out = (float*)d_out;

    ntm_pass1<<<dim3(NBLK, Bc), 256>>>(mem, k, beta, wprev, gamma);
    ntm_pass2<<<dim3(4, Bc), 128>>>(gt, wprev, e, a, out);
}

// round 5
// speedup vs baseline: 1.3343x; 1.0518x over previous
#include <cuda_runtime.h>
#include <math.h>

#define Bc 128
#define Nc 2048
#define Mc 128
#define NBLK 16            // n-blocks per batch (128 rows each)
#define OUT_STRIDE (Mc + 2*Nc)   // 4224

// scratch (static device globals — no allocation allowed)
__device__ float g_exp [Bc * Nc];           // exp(scale*cos) per (b,n)
__device__ float g_part[Bc * NBLK * Mc];    // per-block column partial sums
__device__ float g_bsum[Bc * NBLK];         // per-block partial sum of exp
__device__ float g_bpow[Bc * NBLK];         // per-block partial sum of wprev^gamma

// multi-value butterfly: 16 reductions (8 dots, 8 sqnorms) over 32 lanes.
// Writes exp(scale*cos) for 8 rows, returns warp-summed exp contribution
// (valid on lane 0).
__device__ __forceinline__ float butterfly_exp(
    float r[16], int lane, float scale, float* __restrict__ dst)
{
#pragma unroll
    for (int o = 16, nv = 16; o >= 2; o >>= 1, nv >>= 1) {
        const int half = nv >> 1;
#pragma unroll
        for (int j = 0; j < half; j++) {
            float send = (lane & o) ? r[j] : r[j + half];
            float recv = __shfl_xor_sync(0xFFFFFFFFu, send, o);
            r[j] = ((lane & o) ? r[j + half] : r[j]) + recv;
        }
    }
    r[0] += __shfl_xor_sync(0xFFFFFFFFu, r[0], 1);
    // lanes 2i,2i+1 (i<8) hold dot_i ; lanes 16+2i hold sq_i
    float other = __shfl_xor_sync(0xFFFFFFFFu, r[0], 16);

    float ex = 0.f;
    if ((lane < 16) && !(lane & 1)) {
        int i = lane >> 1;
        ex = __expf(scale * r[0] * rsqrtf(fmaxf(other, 1e-16f)));
        dst[i] = ex;
    }
    ex += __shfl_xor_sync(0xFFFFFFFFu, ex, 2);
    ex += __shfl_xor_sync(0xFFFFFFFFu, ex, 4);
    ex += __shfl_xor_sync(0xFFFFFFFFu, ex, 8);
    return ex;
}

// ---------------------------------------------------------------------------
// Pass 1: single sweep over memory [B,N,M]. Each warp: 16 rows, 2 batches of 8.
// ---------------------------------------------------------------------------
__global__ void __launch_bounds__(256) ntm_pass1(
    const float* __restrict__ mem,   const float* __restrict__ k,
    const float* __restrict__ beta,  const float* __restrict__ wprev,
    const float* __restrict__ gamma)
{
    const int b    = blockIdx.y;
    const int blk  = blockIdx.x;
    const int warp = threadIdx.x >> 5;
    const int lane = threadIdx.x & 31;

    // k row (with eps), 4 elements per lane
    float4 kv = ((const float4*)(k + b * Mc))[lane];
    kv.x += 1e-6f; kv.y += 1e-6f; kv.z += 1e-6f; kv.w += 1e-6f;

    // per-warp nk and scale (redundant across warps, no barrier)
    float kk = kv.x*kv.x + kv.y*kv.y + kv.z*kv.z + kv.w*kv.w;
#pragma unroll
    for (int off = 16; off; off >>= 1)
        kk += __shfl_xor_sync(0xFFFFFFFFu, kk, off);
    const float scale = beta[b] * rsqrtf(fmaxf(kk, 1e-16f));

    const int n0 = blk * 128 + warp * 16;
    const float4* mp = (const float4*)(mem + ((size_t)b * Nc + n0) * Mc);

    // batch 1 loads (rows 0..7), MLP=8
    float4 v[8];
#pragma unroll
    for (int i = 0; i < 8; i++) v[i] = mp[i * 32 + lane];

    float cs0 = 0.f, cs1 = 0.f, cs2 = 0.f, cs3 = 0.f;
    float r1[16];
#pragma unroll
    for (int i = 0; i < 8; i++) {
        float4 t = v[i];
        cs0 += t.x; cs1 += t.y; cs2 += t.z; cs3 += t.w;
        r1[i]     = t.x*kv.x + t.y*kv.y + t.z*kv.z + t.w*kv.w;
        r1[i + 8] = t.x*t.x  + t.y*t.y  + t.z*t.z  + t.w*t.w;
    }

    // batch 2 loads (rows 8..15) in flight while batch-1 butterfly runs
    float4 w[8];
#pragma unroll
    for (int i = 0; i < 8; i++) w[i] = mp[(8 + i) * 32 + lane];

    float ex = butterfly_exp(r1, lane, scale, g_exp + b * Nc + n0);

    float r2[16];
#pragma unroll
    for (int i = 0; i < 8; i++) {
        float4 t = w[i];
        cs0 += t.x; cs1 += t.y; cs2 += t.z; cs3 += t.w;
        r2[i]     = t.x*kv.x + t.y*kv.y + t.z*kv.z + t.w*kv.w;
        r2[i + 8] = t.x*t.x  + t.y*t.y  + t.z*t.z  + t.w*t.w;
    }
    ex += butterfly_exp(r2, lane, scale, g_exp + b * Nc + n0 + 8);

    // wprev^gamma: 128 rows per block -> only threads 0..127 load one row each
    float pw = 0.f;
    if (threadIdx.x < 128)
        pw = __powf(wprev[b * Nc + blk * 128 + threadIdx.x], gamma[b]);
#pragma unroll
    for (int off = 16; off; off >>= 1)
        pw += __shfl_xor_sync(0xFFFFFFFFu, pw, off);

    __shared__ float s_cs[8][Mc];
    __shared__ float s_exw[8];
    __shared__ float s_pww[8];
    {
        int m = lane * 4;
        s_cs[warp][m + 0] = cs0;
        s_cs[warp][m + 1] = cs1;
        s_cs[warp][m + 2] = cs2;
        s_cs[warp][m + 3] = cs3;
        if (lane == 0) { s_exw[warp] = ex; s_pww[warp] = pw; }
    }
    __syncthreads();

    if (threadIdx.x < Mc) {
        float s = 0.f;
#pragma unroll
        for (int wi = 0; wi < 8; wi++) s += s_cs[wi][threadIdx.x];
        g_part[((size_t)b * NBLK + blk) * Mc + threadIdx.x] = s;
    }
    if (threadIdx.x == 0) {
        float se = 0.f, sp = 0.f;
#pragma unroll
        for (int wi = 0; wi < 8; wi++) { se += s_exw[wi]; sp += s_pww[wi]; }
        g_bsum[b * NBLK + blk] = se;
        g_bpow[b * NBLK + blk] = sp;
    }
}

// ---------------------------------------------------------------------------
// Pass 2: one block (512 thr) per batch — single wave, loads prefetched
// before the one scalar reduce.
// ---------------------------------------------------------------------------
__global__ void __launch_bounds__(512) ntm_pass2(
    const float* __restrict__ gt,   const float* __restrict__ wprev,
    const float* __restrict__ e,    const float* __restrict__ a,
    float* __restrict__ out)
{
    const int b   = blockIdx.x;
    const int tid = threadIdx.x;

    // ---- prefetch all elementwise data (independent of the reduce) ----
    const float4 ex = ((const float4*)(g_exp  + b * Nc))[tid];
    const float4 wp = ((const float4*)(wprev + b * Nc))[tid];
    const float  gv = gt[b];

    float evv = 0.f, avv = 0.f, Sm = 0.f;
    if (tid < Mc) {
        evv = e[b * Mc + tid];
        avv = a[b * Mc + tid];
#pragma unroll
        for (int j = 0; j < NBLK; j++)
            Sm += g_part[((size_t)b * NBLK + j) * Mc + tid];
    }

    // ---- one scalar reduce over NBLK=16 partials ----
    __shared__ float s_inv, s_sB;
    if (tid < 32) {
        float es = (tid < NBLK) ? g_bsum[b * NBLK + tid] : 0.f;
        float pw = (tid < NBLK) ? g_bpow[b * NBLK + tid] : 0.f;
#pragma unroll
        for (int off = 8; off; off >>= 1) {
            es += __shfl_xor_sync(0xFFFFFFFFu, es, off);
            pw += __shfl_xor_sync(0xFFFFFFFFu, pw, off);
        }
        if (tid == 0) { s_inv = 1.f / es; s_sB = pw + 1e-6f; }
    }
    __syncthreads();

    const float inv = s_inv;
    const float sB  = s_sB;
    const float og  = 1.f - gv;
    float* ob = out + (size_t)b * OUT_STRIDE;

    ((float4*)(ob + Mc))[tid] = make_float4(sB, sB, sB, sB);
    float4 wg;
    wg.x = gv * ex.x * inv + og * wp.x;
    wg.y = gv * ex.y * inv + og * wp.y;
    wg.z = gv * ex.z * inv + og * wp.z;
    wg.w = gv * ex.w * inv + og * wp.w;
    ((float4*)(ob + Mc + Nc))[tid] = wg;

    if (tid < Mc) {
        // r_t = sB * ((1 - sB*e) * colsum + N * sB * a)
        ob[tid] = sB * ((1.f - sB * evv) * Sm + (float)Nc * sB * avv);
    }
}

extern "C" void kernel_launch(void* const* d_in, const int* in_sizes, int n_in,
                              void* d_out, int out_size)
{
    const float* mem   = (const float*)d_in[0];
    const float* k     = (const float*)d_in[1];
    const float* beta  = (const float*)d_in[2];
    const float* gt    = (const float*)d_in[3];
    const float* wprev = (const float*)d_in[4];
    // d_in[5] = s_t (unused by the reference's live outputs)
    const float* gamma = (const float*)d_in[6];
    const float* e     = (const float*)d_in[7];
    const float* a     = (const float*)d_in[8];
    float* out = (float*)d_out;

    ntm_pass1<<<dim3(NBLK, Bc), 256>>>(mem, k, beta, wprev, gamma);
    ntm_pass2<<<Bc, 512>>>(gt, wprev, e, a, out);
}